// round 17
// baseline (speedup 1.0000x reference)
#include <cuda_runtime.h>
#include <cuda_fp16.h>
#include <cstdint>

#define T_TOK 8192
#define DIM   1024
#define FFD   4096
#define NEXP  8

// ---- static device scratch (no allocations) ----
__device__ int    g_count[NEXP];
__device__ int    g_offset[NEXP];
__device__ int    g_tok[NEXP * T_TOK];
__device__ float  g_gate[NEXP * T_TOK];
__device__ __half g_xh[(size_t)T_TOK * DIM];
__device__ __half g_w1h[(size_t)NEXP * FFD * DIM];
__device__ __half g_w2h[(size_t)NEXP * DIM * FFD];
__device__ __half g_hh[(size_t)T_TOK * 2 * FFD];

__device__ __forceinline__ void cpa16(unsigned dst, const void* src) {
    asm volatile("cp.async.cg.shared.global [%0], [%1], 16;" :: "r"(dst), "l"(src) : "memory");
}
__device__ __forceinline__ void ldsm4(unsigned r[4], unsigned addr) {
    asm volatile("ldmatrix.sync.aligned.m8n8.x4.shared.b16 {%0,%1,%2,%3}, [%4];"
                 : "=r"(r[0]), "=r"(r[1]), "=r"(r[2]), "=r"(r[3]) : "r"(addr));
}
__device__ __forceinline__ void mma_f16(float c[4], const unsigned a[4], unsigned b0, unsigned b1) {
    asm volatile(
        "mma.sync.aligned.m16n8k16.row.col.f32.f16.f16.f32 "
        "{%0,%1,%2,%3}, {%4,%5,%6,%7}, {%8,%9}, {%0,%1,%2,%3};"
        : "+f"(c[0]), "+f"(c[1]), "+f"(c[2]), "+f"(c[3])
        : "r"(a[0]), "r"(a[1]), "r"(a[2]), "r"(a[3]), "r"(b0), "r"(b1));
}
__device__ __forceinline__ void red2(float* p, float v0, float v1) {
    asm volatile("red.global.add.v2.f32 [%0], {%1, %2};" :: "l"(p), "f"(v0), "f"(v1) : "memory");
}

// ---- init routing counters ----
__global__ void k_init() {
    if (threadIdx.x < NEXP) g_count[threadIdx.x] = 0;
}

#define NB_W1   16384
#define NB_W2   16384
#define NB_X    4096
#define NB_GATE 1024

__device__ __forceinline__ void cvt8(const float4* in, uint4* out, int i) {
    float4 a = in[2 * i], b = in[2 * i + 1];
    __half2 h0 = __floats2half2_rn(a.x, a.y);
    __half2 h1 = __floats2half2_rn(a.z, a.w);
    __half2 h2 = __floats2half2_rn(b.x, b.y);
    __half2 h3 = __floats2half2_rn(b.z, b.w);
    uint4 v;
    v.x = *reinterpret_cast<unsigned*>(&h0);
    v.y = *reinterpret_cast<unsigned*>(&h1);
    v.z = *reinterpret_cast<unsigned*>(&h2);
    v.w = *reinterpret_cast<unsigned*>(&h3);
    out[i] = v;
}

// ---- main prep (stream 0): w1 cvt + x cvt + gating (everything g0 needs) ----
__global__ void __launch_bounds__(256)
k_prep_main(const float* __restrict__ x, const float* __restrict__ wg,
            const float* __restrict__ bg, const float* __restrict__ w1,
            float* __restrict__ out, int has_tail) {
    __shared__ float s_wg[NEXP * DIM];
    __shared__ float s_bg[NEXP];
    int b = blockIdx.x, tid = threadIdx.x;

    if (b < NB_W1) {
        cvt8((const float4*)w1, (uint4*)g_w1h, b * 256 + tid);
        return;
    }
    b -= NB_W1;
    if (b < NB_X) {
        cvt8((const float4*)x, (uint4*)g_xh, b * 256 + tid);
        return;
    }
    b -= NB_X;

    // ---- gating: one warp per token, 8 tokens per block ----
    for (int i = tid; i < NEXP * DIM; i += 256) s_wg[i] = wg[i];
    if (tid < NEXP) s_bg[tid] = bg[tid];
    __syncthreads();

    int warp = tid >> 5, lane = tid & 31;
    int t = b * 8 + warp;
    const float* xr = x + (size_t)t * DIM;

    float acc[NEXP];
#pragma unroll
    for (int e = 0; e < NEXP; e++) acc[e] = 0.f;
    for (int d = lane; d < DIM; d += 32) {
        float xv = xr[d];
#pragma unroll
        for (int e = 0; e < NEXP; e++) acc[e] += xv * s_wg[e * DIM + d];
    }
#pragma unroll
    for (int e = 0; e < NEXP; e++) {
#pragma unroll
        for (int o = 16; o > 0; o >>= 1) acc[e] += __shfl_xor_sync(0xffffffffu, acc[e], o);
    }

    if (lane == 0) {
        float p[NEXP];
        float m = -1e30f;
#pragma unroll
        for (int e = 0; e < NEXP; e++) { p[e] = acc[e] + s_bg[e]; m = fmaxf(m, p[e]); }
        float s = 0.f;
#pragma unroll
        for (int e = 0; e < NEXP; e++) { p[e] = expf(p[e] - m); s += p[e]; }
        float inv = 1.f / s;
#pragma unroll
        for (int e = 0; e < NEXP; e++) p[e] *= inv;

        int e1 = 0;
#pragma unroll
        for (int e = 1; e < NEXP; e++) if (p[e] > p[e1]) e1 = e;
        int e2 = (e1 == 0) ? 1 : 0;
#pragma unroll
        for (int e = 0; e < NEXP; e++) if (e != e1 && p[e] > p[e2]) e2 = e;

        int pos1 = atomicAdd(&g_count[e1], 1);
        g_tok[e1 * T_TOK + pos1]  = t;
        g_gate[e1 * T_TOK + pos1] = p[e1];
        int pos2 = atomicAdd(&g_count[e2], 1);
        g_tok[e2 * T_TOK + pos2]  = t;
        g_gate[e2 * T_TOK + pos2] = p[e2];

        if (has_tail) {
            float* tail = out + (size_t)T_TOK * DIM;
            tail[t * 2 + 0] = (float)e1;
            tail[t * 2 + 1] = (float)e2;
            tail[T_TOK * 2 + t * 2 + 0] = p[e1];
            tail[T_TOK * 2 + t * 2 + 1] = p[e2];
        }
    }
}

// ---- side prep (forked stream): w2 cvt + out zeroing (only needed by g1) ----
__global__ void __launch_bounds__(256)
k_prep_side(const float* __restrict__ w2, float* __restrict__ out,
            int out_size, int has_tail, int nb_zero) {
    int b = blockIdx.x, tid = threadIdx.x;
    if (b < NB_W2) {
        cvt8((const float4*)w2, (uint4*)g_w2h, b * 256 + tid);
        return;
    }
    b -= NB_W2;
    int i = (b * 256 + tid) * 4;
    if (i < out_size) {
        const int base = T_TOK * DIM;
        if (!(has_tail && i >= base && i < base + 4 * T_TOK))
            *(float4*)(out + i) = make_float4(0.f, 0.f, 0.f, 0.f);
    }
}

__global__ void k_offsets() {
    int s = 0;
    for (int e = 0; e < NEXP; e++) { g_offset[e] = s; s += g_count[e]; }
}

// ==== GEMM0: x @ w1^T -> h.  256x128 CTA tile, 8 warps x 64x64 warp tile ====
// 256 threads, BK=64, 3-stage cp.async (stage = A 32KB + B 16KB = 48KB), 1 CTA/SM.
__global__ void __launch_bounds__(256, 1)
k_g0(const float* __restrict__ bias) {
    constexpr int KD = DIM, KT = KD / 64;

    int e = blockIdx.z;
    int cnt = g_count[e];
    int m0 = blockIdx.y * 256;
    if (m0 >= cnt) return;
    int n0 = blockIdx.x * 128;
    int off = g_offset[e];

    extern __shared__ __align__(1024) char sm[];
    const unsigned sb = (unsigned)__cvta_generic_to_shared(sm);
    int*   s_tok  = (int*)(sm + 147456);
    float* s_bias = (float*)(sm + 147456 + 1024);

    int tid = threadIdx.x;
    {
        int mc = min(m0 + tid, cnt - 1);
        s_tok[tid] = g_tok[e * T_TOK + mc];
    }
    if (tid < 128) s_bias[tid] = bias[(size_t)e * FFD + n0 + tid];
    __syncthreads();

    const __half* Wb = g_w1h + (size_t)e * FFD * KD;

    int lr = tid >> 3, lc = tid & 7;
    const unsigned soff = (unsigned)(lr * 128 + ((lc ^ (lr & 7)) << 4));
    const __half* bBase = Wb + (size_t)(n0 + lr) * KD + lc * 8;

    auto fill = [&](int j) {
        unsigned ab = sb + (unsigned)(j % 3) * 49152u + soff;
        const int k0 = j * 64;
#pragma unroll
        for (int i = 0; i < 8; i++)
            cpa16(ab + i * 4096, g_xh + (size_t)s_tok[lr + 32 * i] * DIM + lc * 8 + k0);
#pragma unroll
        for (int i = 0; i < 4; i++)
            cpa16(ab + 32768 + i * 4096, bBase + (size_t)i * 32 * KD + k0);
        asm volatile("cp.async.commit_group;" ::: "memory");
    };

    int warp = tid >> 5, lane = tid & 31;
    int g = lane >> 2, tg = lane & 3;
    int wm = (warp & 3) * 64, wn = (warp >> 2) * 64;
    int sub = lane >> 3, rin = lane & 7;
    int arow[4], brow[4];
#pragma unroll
    for (int mi = 0; mi < 4; mi++) arow[mi] = wm + mi * 16 + ((sub & 1) << 3) + rin;
#pragma unroll
    for (int bj = 0; bj < 4; bj++) brow[bj] = wn + bj * 16 + ((sub >> 1) << 3) + rin;
    int qA = sub >> 1, qB = sub & 1;

    float c[4][8][4];
#pragma unroll
    for (int mi = 0; mi < 4; mi++)
#pragma unroll
        for (int nj = 0; nj < 8; nj++)
#pragma unroll
            for (int q = 0; q < 4; q++) c[mi][nj][q] = 0.f;

    fill(0); fill(1);

    for (int ki = 0; ki < KT; ki++) {
        asm volatile("cp.async.wait_group %0;" :: "n"(1) : "memory");
        __syncthreads();
        if (ki + 2 < KT) fill(ki + 2);
        else asm volatile("cp.async.commit_group;" ::: "memory");

        unsigned As = sb + (unsigned)(ki % 3) * 49152u;
        unsigned Bs = As + 32768u;
#pragma unroll
        for (int kc = 0; kc < 4; kc++) {
            unsigned a[4][4], b[4][4];
#pragma unroll
            for (int mi = 0; mi < 4; mi++)
                ldsm4(a[mi], As + arow[mi] * 128 + (((kc * 2 + qA) ^ (arow[mi] & 7)) << 4));
#pragma unroll
            for (int bj = 0; bj < 4; bj++)
                ldsm4(b[bj], Bs + brow[bj] * 128 + (((kc * 2 + qB) ^ (brow[bj] & 7)) << 4));
#pragma unroll
            for (int mi = 0; mi < 4; mi++)
#pragma unroll
                for (int nj = 0; nj < 8; nj++) {
                    const unsigned* bb = b[nj >> 1];
                    if (nj & 1) mma_f16(c[mi][nj], a[mi], bb[2], bb[3]);
                    else        mma_f16(c[mi][nj], a[mi], bb[0], bb[1]);
                }
        }
    }

    // epilogue -> h (fp16, leaky + bias)
#pragma unroll
    for (int mi = 0; mi < 4; mi++) {
#pragma unroll
        for (int rr = 0; rr < 2; rr++) {
            int mloc = wm + mi * 16 + g + rr * 8;
            if (m0 + mloc >= cnt) continue;
            __half* hrow = g_hh + (size_t)(off + m0 + mloc) * FFD + n0;
#pragma unroll
            for (int nj = 0; nj < 8; nj++) {
                int n = wn + nj * 8 + 2 * tg;
                float v0 = c[mi][nj][rr * 2 + 0] + s_bias[n];
                float v1 = c[mi][nj][rr * 2 + 1] + s_bias[n + 1];
                v0 = v0 > 0.f ? v0 : 0.1f * v0;
                v1 = v1 > 0.f ? v1 : 0.1f * v1;
                *(__half2*)(hrow + n) = __floats2half2_rn(v0, v1);
            }
        }
    }
}

// ==== GEMM1: h @ w2^T -> out.  128x128 CTA tile, 8 warps x 32x64 warp tile ====
// (proven R14 shape: 256 threads, BK=64, 3-stage, 2 CTAs/SM)
__global__ void __launch_bounds__(256, 2)
k_g1(const float* __restrict__ bias, float* __restrict__ out) {
    constexpr int KD = FFD, KT = KD / 64;

    int e = blockIdx.z;
    int cnt = g_count[e];
    int m0 = blockIdx.y * 128;
    if (m0 >= cnt) return;
    int n0 = blockIdx.x * 128;
    int off = g_offset[e];

    extern __shared__ __align__(1024) char sm[];
    const unsigned sb = (unsigned)__cvta_generic_to_shared(sm);
    int*   s_tok  = (int*)(sm + 98304);
    float* s_gate = (float*)(sm + 98304 + 512);
    float* s_bias = (float*)(sm + 98304 + 1024);

    int tid = threadIdx.x;
    if (tid < 128) {
        int mc = min(m0 + tid, cnt - 1);
        s_tok[tid]  = g_tok[e * T_TOK + mc];
        s_gate[tid] = g_gate[e * T_TOK + mc];
        s_bias[tid] = bias[(size_t)e * DIM + n0 + tid];
    }
    __syncthreads();

    const __half* Wb = g_w2h + (size_t)e * DIM * KD;

    int lr = tid >> 3, lc = tid & 7;
    const __half* aP[4];
    const __half* bP[4];
#pragma unroll
    for (int i = 0; i < 4; i++) {
        int r = lr + 32 * i;
        aP[i] = g_hh + (size_t)(off + min(m0 + r, cnt - 1)) * FFD + lc * 8;
        bP[i] = Wb + (size_t)(n0 + r) * KD + lc * 8;
    }
    const unsigned soff = (unsigned)(lr * 128 + ((lc ^ (lr & 7)) << 4));

    auto fill = [&](int j) {
        unsigned ab = sb + (unsigned)(j % 3) * 32768u + soff;
        const int k0 = j * 64;
#pragma unroll
        for (int i = 0; i < 4; i++) {
            cpa16(ab + i * 4096, aP[i] + k0);
            cpa16(ab + 16384 + i * 4096, bP[i] + k0);
        }
        asm volatile("cp.async.commit_group;" ::: "memory");
    };

    int warp = tid >> 5, lane = tid & 31;
    int g = lane >> 2, tg = lane & 3;
    int wm = (warp & 3) * 32, wn = (warp >> 2) * 64;
    int sub = lane >> 3, rin = lane & 7;
    int arow[2], brow[4];
#pragma unroll
    for (int mi = 0; mi < 2; mi++) arow[mi] = wm + mi * 16 + ((sub & 1) << 3) + rin;
#pragma unroll
    for (int bj = 0; bj < 4; bj++) brow[bj] = wn + bj * 16 + ((sub >> 1) << 3) + rin;
    int qA = sub >> 1, qB = sub & 1;

    float c[2][8][4];
#pragma unroll
    for (int mi = 0; mi < 2; mi++)
#pragma unroll
        for (int nj = 0; nj < 8; nj++)
#pragma unroll
            for (int q = 0; q < 4; q++) c[mi][nj][q] = 0.f;

    fill(0); fill(1);

    for (int ki = 0; ki < KT; ki++) {
        asm volatile("cp.async.wait_group %0;" :: "n"(1) : "memory");
        __syncthreads();
        if (ki + 2 < KT) fill(ki + 2);
        else asm volatile("cp.async.commit_group;" ::: "memory");

        unsigned As = sb + (unsigned)(ki % 3) * 32768u;
        unsigned Bs = As + 16384u;
#pragma unroll
        for (int kc = 0; kc < 4; kc++) {
            unsigned a[2][4], b[4][4];
#pragma unroll
            for (int mi = 0; mi < 2; mi++)
                ldsm4(a[mi], As + arow[mi] * 128 + (((kc * 2 + qA) ^ (arow[mi] & 7)) << 4));
#pragma unroll
            for (int bj = 0; bj < 4; bj++)
                ldsm4(b[bj], Bs + brow[bj] * 128 + (((kc * 2 + qB) ^ (brow[bj] & 7)) << 4));
#pragma unroll
            for (int mi = 0; mi < 2; mi++)
#pragma unroll
                for (int nj = 0; nj < 8; nj++) {
                    const unsigned* bb = b[nj >> 1];
                    if (nj & 1) mma_f16(c[mi][nj], a[mi], bb[2], bb[3]);
                    else        mma_f16(c[mi][nj], a[mi], bb[0], bb[1]);
                }
        }
    }

    // epilogue -> red.v2 scatter
#pragma unroll
    for (int mi = 0; mi < 2; mi++) {
#pragma unroll
        for (int rr = 0; rr < 2; rr++) {
            int mloc = wm + mi * 16 + g + rr * 8;
            if (m0 + mloc >= cnt) continue;
            int tok = s_tok[mloc];
            float gt = s_gate[mloc];
            float* orow = out + (size_t)tok * DIM + n0;
#pragma unroll
            for (int nj = 0; nj < 8; nj++) {
                int n = wn + nj * 8 + 2 * tg;
                red2(orow + n, (c[mi][nj][rr * 2 + 0] + s_bias[n]) * gt,
                               (c[mi][nj][rr * 2 + 1] + s_bias[n + 1]) * gt);
            }
        }
    }
}

extern "C" void kernel_launch(void* const* d_in, const int* in_sizes, int n_in,
                              void* d_out, int out_size) {
    const float* x  = (const float*)d_in[0];
    const float* wg = (const float*)d_in[1];
    const float* bg = (const float*)d_in[2];
    const float* w1 = (const float*)d_in[3];
    const float* b1 = (const float*)d_in[4];
    const float* w2 = (const float*)d_in[5];
    const float* b2 = (const float*)d_in[6];
    float* out = (float*)d_out;

    const int base = T_TOK * DIM;
    int has_tail = (out_size >= base + 4 * T_TOK) ? 1 : 0;
    int nb_zero = (out_size / 4 + 255) / 256;

    const int SMEM0 = 3 * 49152 + 2048;
    const int SMEM1 = 3 * 32768 + 2048;
    cudaFuncSetAttribute(k_g0, cudaFuncAttributeMaxDynamicSharedMemorySize, SMEM0);
    cudaFuncSetAttribute(k_g1, cudaFuncAttributeMaxDynamicSharedMemorySize, SMEM1);

    // side stream + fork/join events (created once, on the uncaptured first call)
    static cudaStream_t s1 = nullptr;
    static cudaEvent_t evF = nullptr, evJ = nullptr;
    if (s1 == nullptr) {
        cudaStreamCreateWithFlags(&s1, cudaStreamNonBlocking);
        cudaEventCreateWithFlags(&evF, cudaEventDisableTiming);
        cudaEventCreateWithFlags(&evJ, cudaEventDisableTiming);
    }

    k_init<<<1, 32>>>();
    cudaEventRecord(evF, 0);
    cudaStreamWaitEvent(s1, evF, 0);
    // side: w2 conversion + output zeroing — overlaps main prep + g0
    k_prep_side<<<NB_W2 + nb_zero, 256, 0, s1>>>(w2, out, out_size, has_tail, nb_zero);
    // main: w1/x conversion + gating
    k_prep_main<<<NB_W1 + NB_X + NB_GATE, 256>>>(x, wg, bg, w1, out, has_tail);
    k_offsets<<<1, 1>>>();
    k_g0<<<dim3(FFD / 128, T_TOK / 256, NEXP), 256, SMEM0>>>(b1);
    cudaEventRecord(evJ, s1);
    cudaStreamWaitEvent(0, evJ, 0);
    k_g1<<<dim3(DIM / 128, T_TOK / 128, NEXP), 256, SMEM1>>>(b2, out);
}